// round 4
// baseline (speedup 1.0000x reference)
#include <cuda_runtime.h>
#include <cstddef>

// CopyMechanism: out[b,t,:] = sigmoid(gate) * vocab_dists[b,t,:]
//                then out[b,t, src_ids[b,t,s]] += (1-sigmoid(gate)) * attn_dists[b,t,s]
//
// Shapes: B=16, T=128, H=512, V=32000, S=400. Output f32 [B,T,V].
// One block per row (b,t): the scatter only touches addresses this block
// wrote in the streaming phase, so a __syncthreads() provides ordering.

#define CM_B 16
#define CM_T 128
#define CM_H 512
#define CM_V 32000
#define CM_S 400
#define CM_ROWS (CM_B * CM_T)
#define CM_THREADS 512

__global__ __launch_bounds__(CM_THREADS, 2)
void copy_mechanism_kernel(
    const float* __restrict__ ctx,    // [ROWS, H]
    const float* __restrict__ hid,    // [ROWS, H]
    const float* __restrict__ emb,    // [ROWS, H]
    const float* __restrict__ vocab,  // [ROWS, V]
    const float* __restrict__ attn,   // [ROWS, S]
    const int*   __restrict__ src,    // [ROWS, S]
    const float* __restrict__ w_h,    // [H]
    const float* __restrict__ w_s,    // [H]
    const float* __restrict__ w_x,    // [H]
    const float* __restrict__ w_b,    // [1]
    float*       __restrict__ out)    // [ROWS, V]
{
    const int r   = blockIdx.x;
    const int tid = threadIdx.x;

    __shared__ float red[CM_THREADS / 32];
    __shared__ float s_pgen;

    // ---- Phase 1: gate logit (3 dot products over H=512) ----
    const float* crow = ctx + (size_t)r * CM_H;
    const float* hrow = hid + (size_t)r * CM_H;
    const float* erow = emb + (size_t)r * CM_H;

    float acc = 0.0f;
    // H == CM_THREADS: exactly one element per thread
    {
        int i = tid;
        acc = fmaf(crow[i], w_h[i],
              fmaf(hrow[i], w_s[i],
                   erow[i] * w_x[i]));
    }
    #pragma unroll
    for (int o = 16; o > 0; o >>= 1)
        acc += __shfl_xor_sync(0xffffffffu, acc, o);
    if ((tid & 31) == 0) red[tid >> 5] = acc;
    __syncthreads();
    if (tid == 0) {
        float s = w_b[0];
        #pragma unroll
        for (int w = 0; w < CM_THREADS / 32; w++) s += red[w];
        s_pgen = 1.0f / (1.0f + expf(-s));
    }
    __syncthreads();
    const float p = s_pgen;

    // ---- Phase 2: stream out = p * vocab (float4, V/4 = 8000 per row) ----
    const float4* __restrict__ vin  = (const float4*)(vocab + (size_t)r * CM_V);
    float4*       __restrict__ vout = (float4*)(out   + (size_t)r * CM_V);

    #pragma unroll 4
    for (int i = tid; i < CM_V / 4; i += CM_THREADS) {
        float4 v = vin[i];
        v.x *= p; v.y *= p; v.z *= p; v.w *= p;
        vout[i] = v;
    }
    __syncthreads();  // scatter below reads/modifies addresses written above (same block)

    // ---- Phase 3: scatter-add (1-p)*attn into this row ----
    const float q = 1.0f - p;
    float*       orow = out  + (size_t)r * CM_V;
    const float* arow = attn + (size_t)r * CM_S;
    const int*   srow = src  + (size_t)r * CM_S;

    for (int i = tid; i < CM_S; i += CM_THREADS) {
        atomicAdd(orow + srow[i], q * arow[i]);
    }
}

extern "C" void kernel_launch(void* const* d_in, const int* in_sizes, int n_in,
                              void* d_out, int out_size)
{
    // Front inputs (fixed positions):
    const float* ctx   = (const float*)d_in[0];  // context_vecs [B,T,H]
    const float* hid   = (const float*)d_in[1];  // hidden       [B,T,H]
    const float* emb   = (const float*)d_in[2];  // trg_embs     [B,T,H]
    const float* vocab = (const float*)d_in[3];  // vocab_dists  [B,T,V]
    const float* attn  = (const float*)d_in[4];  // attn_dists   [B,T,S]
    const int*   src   = (const int*)  d_in[5];  // src_ids      [B,T,S]
    // pad_id (unused by the reference) may or may not occupy a slot;
    // index the weights from the END so both layouts work.
    const float* w_h = (const float*)d_in[n_in - 4];  // [1,H]
    const float* w_s = (const float*)d_in[n_in - 3];  // [1,H]
    const float* w_x = (const float*)d_in[n_in - 2];  // [1,H]
    const float* w_b = (const float*)d_in[n_in - 1];  // [1]

    float* out = (float*)d_out;

    copy_mechanism_kernel<<<CM_ROWS, CM_THREADS>>>(
        ctx, hid, emb, vocab, attn, src, w_h, w_s, w_x, w_b, out);
}